// round 13
// baseline (speedup 1.0000x reference)
#include <cuda_runtime.h>
#include <cstdint>

// VQ quantize via mma.sync tf32 (3xTF32 split = fp32-grade scores).
// TPB=256 / M_TILE=128 / 2 CTAs per SM; B streamed via 32KB cp.async chunks.
// Non-volatile MMA asm + unroll-2 nc loop so ptxas can interleave epilogues
// under MMAs. Score arithmetic bit-identical to R8/R10-R12.
// Out f32: quantize (8388608) | diff (1) | embed_ind (131072).

#define DIMK 64
#define NCODE 512
#define NROWS (32 * 64 * 64)
#define NTOT (NROWS * DIMK)
#define TPB 256
#define M_TILE 128
#define NBLK (NROWS / M_TILE)   // 1024
#define CF4 2048                 // float4 per 32KB chunk (8 nc-blocks)

#define SM_B0 0                          // 32768
#define SM_B1 32768                      // 32768
#define SM_NRM 65536                     // 2048
#define SM_WIN (SM_NRM + 2048)           // 512
#define SM_RED (SM_WIN + 512)            // 1024
#define SM_BYTES (SM_RED + 1024)         // 69120

__device__ __align__(16) float4 g_Bfrag[64 * 8 * 32];   // [nc][kc][lane] = {bh0,bh1,bl0,bl1}
__device__ __align__(16) float g_embT[NCODE * DIMK];
__device__ float g_nrm[NCODE];
__device__ unsigned long long g_diff_acc;
__device__ unsigned int g_ticket;

__device__ __forceinline__ uint32_t smem_u32(const void* p) {
    uint32_t a;
    asm("{ .reg .u64 t; cvta.to.shared.u64 t, %1; cvt.u32.u64 %0, t; }" : "=r"(a) : "l"(p));
    return a;
}
__device__ __forceinline__ uint32_t tf32_hi(float f) {
    uint32_t r;
    asm("cvt.rna.tf32.f32 %0, %1;" : "=r"(r) : "f"(f));
    return r;
}
// NON-volatile: pure register op, lets ptxas schedule/interleave freely.
// FP result unchanged: each accumulator's chain order is fixed by data deps.
__device__ __forceinline__ void mma8(float* c, const uint32_t* a, uint32_t b0, uint32_t b1) {
    asm("mma.sync.aligned.m16n8k8.row.col.f32.tf32.tf32.f32 "
        "{%0,%1,%2,%3}, {%4,%5,%6,%7}, {%8,%9}, {%0,%1,%2,%3};"
        : "+f"(c[0]), "+f"(c[1]), "+f"(c[2]), "+f"(c[3])
        : "r"(a[0]), "r"(a[1]), "r"(a[2]), "r"(a[3]), "r"(b0), "r"(b1));
}
__device__ __forceinline__ void cp16(uint32_t s, const void* g) {
    asm volatile("cp.async.cg.shared.global [%0], [%1], 16;" :: "r"(s), "l"(g) : "memory");
}
#define CP_COMMIT() asm volatile("cp.async.commit_group;" ::: "memory")
#define CP_WAIT1()  asm volatile("cp.async.wait_group 1;" ::: "memory")
#define CP_WAIT0()  asm volatile("cp.async.wait_group 0;" ::: "memory")

// ---- prep: parallel across 64 blocks ----
__global__ void vq_prep(const float* __restrict__ embed) {
    int gtid = blockIdx.x * blockDim.x + threadIdx.x;   // 64*256 = 16384

    if (gtid < NCODE) {
        int t = gtid;
        float nr = 0.f;
        for (int d = 0; d < DIMK; d++) {
            float e = embed[d * NCODE + t];
            g_embT[t * DIMK + d] = e;
            nr = fmaf(e, e, nr);
        }
        g_nrm[t] = nr;
    }

    int i = gtid;   // [nc][kc][lane]
    int lane = i & 31;
    int kc = (i >> 5) & 7;
    int nc = i >> 8;
    int gid = lane >> 2, tig = lane & 3;
    int n = nc * 8 + gid;
    int k0 = kc * 8 + tig;
    float v0 = -2.f * embed[k0 * NCODE + n];
    float v1 = -2.f * embed[(k0 + 4) * NCODE + n];
    uint32_t h0 = tf32_hi(v0), h1 = tf32_hi(v1);
    uint32_t l0 = tf32_hi(v0 - __uint_as_float(h0));
    uint32_t l1 = tf32_hi(v1 - __uint_as_float(h1));
    float4 f;
    f.x = __uint_as_float(h0);
    f.y = __uint_as_float(h1);
    f.z = __uint_as_float(l0);
    f.w = __uint_as_float(l1);
    g_Bfrag[i] = f;
}

__global__ __launch_bounds__(TPB, 2)
void vq_mma_kernel(const float* __restrict__ x,
                   float* __restrict__ out,
                   int out_size) {
    extern __shared__ char smem[];
    float* nsm = (float*)(smem + SM_NRM);
    int* WIN = (int*)(smem + SM_WIN);
    float* red = (float*)(smem + SM_RED);

    int tid = threadIdx.x, wid = tid >> 5, lane = tid & 31;
    int gid = lane >> 2, tig = lane & 3;
    int base_row = blockIdx.x * M_TILE;

    // async load of B chunk 0 into ping
    {
        uint32_t dst = smem_u32(smem + SM_B0) + tid * 16;
        const float4* src = g_Bfrag + tid;
#pragma unroll
        for (int i = 0; i < CF4 / TPB; i++)
            cp16(dst + i * TPB * 16, src + i * TPB);
        CP_COMMIT();
    }

    for (int i = tid; i < NCODE; i += TPB) nsm[i] = g_nrm[i];

    // A fragments (tf32 hi/lo): ONE m16 tile per warp, direct from gmem.
    int m0 = wid * 16;
    uint32_t Ah[8][4], Al[8][4];
    {
        const float* xr0 = x + (size_t)(base_row + m0 + gid) * DIMK;
        const float* xr8 = xr0 + 8 * DIMK;
#pragma unroll
        for (int kc = 0; kc < 8; kc++) {
            int c0 = kc * 8 + tig;
            float f[4];
            f[0] = __ldg(xr0 + c0);
            f[1] = __ldg(xr8 + c0);
            f[2] = __ldg(xr0 + c0 + 4);
            f[3] = __ldg(xr8 + c0 + 4);
#pragma unroll
            for (int j = 0; j < 4; j++) {
                uint32_t h = tf32_hi(f[j]);
                Ah[kc][j] = h;
                Al[kc][j] = tf32_hi(f[j] - __uint_as_float(h));
            }
        }
    }

    float best[2];
    int bi[2];
    best[0] = best[1] = __int_as_float(0x7f800000);
    bi[0] = bi[1] = 0;

#pragma unroll 1
    for (int c = 0; c < 8; c++) {
        if (c < 7) {
            uint32_t dst = smem_u32(smem + ((c & 1) ? SM_B0 : SM_B1)) + tid * 16;
            const float4* src = g_Bfrag + (c + 1) * CF4 + tid;
#pragma unroll
            for (int i = 0; i < CF4 / TPB; i++)
                cp16(dst + i * TPB * 16, src + i * TPB);
            CP_COMMIT();
            CP_WAIT1();
        } else {
            CP_WAIT0();
        }
        __syncthreads();

        const float4* Bq = (const float4*)(smem + ((c & 1) ? SM_B1 : SM_B0));

#pragma unroll 2
        for (int ncl = 0; ncl < 8; ncl++) {
            float4 b[8];
#pragma unroll
            for (int kc = 0; kc < 8; kc++) b[kc] = Bq[(ncl * 8 + kc) * 32 + lane];

            // bit-identical score arithmetic (acc from 0, kc order 0..7, norm last)
            float hh[4] = {0, 0, 0, 0}, lh[4] = {0, 0, 0, 0}, hl[4] = {0, 0, 0, 0};
#pragma unroll
            for (int kc = 0; kc < 8; kc++) {
                uint32_t bh0 = __float_as_uint(b[kc].x), bh1 = __float_as_uint(b[kc].y);
                uint32_t bl0 = __float_as_uint(b[kc].z), bl1 = __float_as_uint(b[kc].w);
                mma8(hh, Ah[kc], bh0, bh1);
                mma8(lh, Al[kc], bh0, bh1);
                mma8(hl, Ah[kc], bl0, bl1);
            }
            int n0 = (c * 8 + ncl) * 8;
            float2 nv = *(const float2*)(nsm + n0 + 2 * tig);
            int ca = n0 + 2 * tig, cb = ca + 1;
            float s;
            s = ((lh[0] + hl[0]) + hh[0]) + nv.x; if (s < best[0]) { best[0] = s; bi[0] = ca; }
            s = ((lh[1] + hl[1]) + hh[1]) + nv.y; if (s < best[0]) { best[0] = s; bi[0] = cb; }
            s = ((lh[2] + hl[2]) + hh[2]) + nv.x; if (s < best[1]) { best[1] = s; bi[1] = ca; }
            s = ((lh[3] + hl[3]) + hh[3]) + nv.y; if (s < best[1]) { best[1] = s; bi[1] = cb; }
        }
        __syncthreads();
    }

    // reduce across the 4 lanes of each quad (j=0: row gid, j=1: row gid+8)
#pragma unroll
    for (int j = 0; j < 2; j++) {
        float b = best[j];
        int ix = bi[j];
#pragma unroll
        for (int o = 1; o < 4; o <<= 1) {
            float ob = __shfl_xor_sync(0xffffffffu, b, o);
            int oi = __shfl_xor_sync(0xffffffffu, ix, o);
            if (ob < b || (ob == b && oi < ix)) { b = ob; ix = oi; }
        }
        if (tig == 0) WIN[m0 + j * 8 + gid] = ix;
    }
    __syncthreads();

    // phase 2: quantize writes + diff + ind (16 rows per warp)
    float dsum = 0.f;
    bool write_ind = (out_size >= NTOT + 1 + NROWS);
#pragma unroll 1
    for (int i = 0; i < 16; i++) {
        int r = wid * 16 + i;
        int bk = WIN[r];
        size_t n = (size_t)base_row + r;
        float2 ev = ((const float2*)(g_embT + bk * DIMK))[lane];
        float2 xv = ((const float2*)(x + n * DIMK))[lane];
        ((float2*)(out + n * DIMK))[lane] = ev;
        float dx = ev.x - xv.x, dy = ev.y - xv.y;
        dsum = fmaf(dx, dx, dsum);
        dsum = fmaf(dy, dy, dsum);
        if (lane == 0 && write_ind) out[NTOT + 1 + n] = (float)bk;
    }

    red[tid] = dsum;
    __syncthreads();
#pragma unroll
    for (int s = TPB / 2; s > 0; s >>= 1) {
        if (tid < s) red[tid] += red[tid + s];
        __syncthreads();
    }
    if (tid == 0) {
        unsigned long long q2 = (unsigned long long)((double)red[0] * 1048576.0 + 0.5);
        atomicAdd(&g_diff_acc, q2);
        __threadfence();
        unsigned t = atomicAdd(&g_ticket, 1u);
        if (t == (unsigned)(NBLK - 1)) {
            unsigned long long tot = atomicExch(&g_diff_acc, 0ull);
            atomicExch(&g_ticket, 0u);
            if (out_size >= NTOT + 1)
                out[NTOT] = (float)((double)tot * (1.0 / 1048576.0) / (double)NTOT);
        }
    }
}

extern "C" void kernel_launch(void* const* d_in, const int* in_sizes, int n_in,
                              void* d_out, int out_size) {
    const float* x = (const float*)d_in[0];
    const float* embed = (const float*)d_in[1];
    float* out = (float*)d_out;

    cudaFuncSetAttribute(vq_mma_kernel,
                         cudaFuncAttributeMaxDynamicSharedMemorySize, SM_BYTES);

    vq_prep<<<64, 256>>>(embed);
    vq_mma_kernel<<<NBLK, TPB, SM_BYTES>>>(x, out, out_size);
}